// round 1
// baseline (speedup 1.0000x reference)
#include <cuda_runtime.h>

#define NN   4096
#define IND  256
#define HID1 64
#define NH1  4
#define F1T  256
#define F2T  128

typedef unsigned long long u64;

// ---- scratch (device globals; no allocation allowed) ----
__device__ float g_Wh1[NN * F1T];   // layer-1 Wh, heads concatenated
__device__ float g_f1h[NH1 * NN];
__device__ float g_f2h[NH1 * NN];
__device__ float g_h1 [NN * F1T];   // layer-1 output (after ELU)
__device__ float g_Wh2[NN * F2T];
__device__ float g_f1o[NN];
__device__ float g_f2o[NN];

// ---- packed fp32x2 helpers (sm_103a) ----
__device__ __forceinline__ u64 pack2(float lo, float hi) {
    return (u64)__float_as_uint(lo) | ((u64)__float_as_uint(hi) << 32);
}
__device__ __forceinline__ float lo2(u64 v) { return __uint_as_float((unsigned)v); }
__device__ __forceinline__ float hi2(u64 v) { return __uint_as_float((unsigned)(v >> 32)); }
__device__ __forceinline__ u64 fma2(u64 a, u64 b, u64 c) {
    u64 d;
    asm("fma.rn.f32x2 %0, %1, %2, %3;" : "=l"(d) : "l"(a), "l"(b), "l"(c));
    return d;
}

// =======================================================================
// GEMM: C[4096, FCOLS] = A[4096,256] @ B    (block = 64 rows, 256 threads)
// =======================================================================
template <int FCOLS, bool HEADS_B>
__device__ __forceinline__ void gemm_body(const float* __restrict__ A,
                                          const float* __restrict__ B,
                                          float* __restrict__ C) {
    constexpr int K = 256, XPAD = 68;
    constexpr int NRG = 256 / FCOLS;
    constexpr int RPT = 64 / NRG;            // rows per thread
    const int tid  = threadIdx.x;
    const int col  = tid % FCOLS;
    const int r0t  = (tid / FCOLS) * RPT;
    const int row0 = blockIdx.x * 64;

    __shared__ float x_s[32 * XPAD];         // [kk][r], padded

    u64 acc[RPT / 2];
#pragma unroll
    for (int j = 0; j < RPT / 2; j++) acc[j] = 0ull;

    for (int k0 = 0; k0 < K; k0 += 32) {
        __syncthreads();
#pragma unroll
        for (int i = 0; i < 8; i++) {
            int idx = i * 256 + tid;
            int r = idx >> 5, kk = idx & 31;
            x_s[kk * XPAD + r] = A[(row0 + r) * K + k0 + kk];
        }
        float bv[32];
#pragma unroll
        for (int kk = 0; kk < 32; kk++)
            bv[kk] = HEADS_B
                   ? B[(col >> 6) * (IND * HID1) + (k0 + kk) * HID1 + (col & 63)]
                   : B[(k0 + kk) * FCOLS + col];
        __syncthreads();
#pragma unroll
        for (int kk = 0; kk < 32; kk++) {
            u64 b2 = pack2(bv[kk], bv[kk]);
            const float* xb = &x_s[kk * XPAD + r0t];
#pragma unroll
            for (int c = 0; c < RPT / 4; c++) {
                ulonglong2 xv = *(const ulonglong2*)(xb + 4 * c);
                acc[2 * c]     = fma2(xv.x, b2, acc[2 * c]);
                acc[2 * c + 1] = fma2(xv.y, b2, acc[2 * c + 1]);
            }
        }
    }
#pragma unroll
    for (int j = 0; j < RPT / 2; j++) {
        C[(row0 + r0t + 2 * j)     * FCOLS + col] = lo2(acc[j]);
        C[(row0 + r0t + 2 * j + 1) * FCOLS + col] = hi2(acc[j]);
    }
}

__global__ void __launch_bounds__(256) gemm1_k(const float* __restrict__ x,
                                               const float* __restrict__ W_heads) {
    gemm_body<F1T, true>(x, W_heads, g_Wh1);
}
__global__ void __launch_bounds__(256) gemm2_k(const float* __restrict__ W_out) {
    gemm_body<F2T, false>(g_h1, W_out, g_Wh2);
}

// =======================================================================
// f-vector kernels: f1[i] = Wh[i,:] . a[:F], f2[i] = Wh[i,:] . a[F:]
// =======================================================================
__global__ void fvec1_k(const float* __restrict__ a_heads) {
    const int i = blockIdx.x;
    const int t = threadIdx.x;            // 0..63
    const int lane = t & 31, w = t >> 5;
    float p1[NH1], p2[NH1];
#pragma unroll
    for (int h = 0; h < NH1; h++) {
        float v = g_Wh1[i * F1T + h * HID1 + t];
        p1[h] = v * a_heads[h * (2 * HID1) + t];
        p2[h] = v * a_heads[h * (2 * HID1) + HID1 + t];
    }
#pragma unroll
    for (int off = 16; off; off >>= 1)
#pragma unroll
        for (int h = 0; h < NH1; h++) {
            p1[h] += __shfl_down_sync(0xffffffffu, p1[h], off);
            p2[h] += __shfl_down_sync(0xffffffffu, p2[h], off);
        }
    __shared__ float red[2][2 * NH1];
    if (lane == 0) {
#pragma unroll
        for (int h = 0; h < NH1; h++) { red[w][h] = p1[h]; red[w][NH1 + h] = p2[h]; }
    }
    __syncthreads();
    if (t == 0) {
#pragma unroll
        for (int h = 0; h < NH1; h++) {
            g_f1h[h * NN + i] = red[0][h] + red[1][h];
            g_f2h[h * NN + i] = red[0][NH1 + h] + red[1][NH1 + h];
        }
    }
}

__global__ void fvec2_k(const float* __restrict__ a_out) {
    const int i = blockIdx.x;
    const int t = threadIdx.x;            // 0..127
    const int lane = t & 31, w = t >> 5;
    float v  = g_Wh2[i * F2T + t];
    float p1 = v * a_out[t];
    float p2 = v * a_out[F2T + t];
#pragma unroll
    for (int off = 16; off; off >>= 1) {
        p1 += __shfl_down_sync(0xffffffffu, p1, off);
        p2 += __shfl_down_sync(0xffffffffu, p2, off);
    }
    __shared__ float red[4][2];
    if (lane == 0) { red[w][0] = p1; red[w][1] = p2; }
    __syncthreads();
    if (t == 0) {
        g_f1o[i] = red[0][0] + red[1][0] + red[2][0] + red[3][0];
        g_f2o[i] = red[0][1] + red[1][1] + red[2][1] + red[3][1];
    }
}

// =======================================================================
// Fused masked-softmax attention + aggregation + ELU (flash style)
// block = 32 rows (TI) x all F_TOT feats, 256 threads, stream 32-wide j-tiles
// =======================================================================
template <int F_TOT, int NH>
__device__ __forceinline__ void attn_body(const int* __restrict__ adj,
                                          const float* __restrict__ Wh,
                                          const float* __restrict__ f1,
                                          const float* __restrict__ f2,
                                          float* __restrict__ out) {
    constexpr int TI = 32, TJ = 32, PPAD = 36;
    constexpr int HID = F_TOT / NH;
    constexpr int NRG = 256 / F_TOT;
    constexpr int RPT = TI / NRG;                // acc rows per thread
    const int tid  = threadIdx.x;
    const int lane = tid & 31, warp = tid >> 5;
    const int row0 = blockIdx.x * TI;
    const int feat = tid % F_TOT;
    const int r0t  = (tid / F_TOT) * RPT;
    const int hh   = feat / HID;

    __shared__ float p_s[NH * TJ * PPAD];        // [h][jj][r], padded 36
    __shared__ float denom_s[TI * NH];

    u64 acc[RPT / 2];
#pragma unroll
    for (int j = 0; j < RPT / 2; j++) acc[j] = 0ull;

    float dpart[4][NH];                          // per-(r,jj=lane) denom partials
#pragma unroll
    for (int q = 0; q < 4; q++)
#pragma unroll
        for (int h = 0; h < NH; h++) dpart[q][h] = 0.0f;

    float f1r[4][NH];                            // f1 for this thread's p rows
#pragma unroll
    for (int q = 0; q < 4; q++)
#pragma unroll
        for (int h = 0; h < NH; h++)
            f1r[q][h] = f1[h * NN + row0 + q * 8 + warp];

    for (int j0 = 0; j0 < NN; j0 += TJ) {
        // ---- p phase: thread handles (jj = lane, r = q*8 + warp) ----
        float f2v[NH];
#pragma unroll
        for (int h = 0; h < NH; h++) f2v[h] = f2[h * NN + j0 + lane];
#pragma unroll
        for (int q = 0; q < 4; q++) {
            const int r = q * 8 + warp;
            const int m = adj[(row0 + r) * NN + j0 + lane];
#pragma unroll
            for (int h = 0; h < NH; h++) {
                float s = f1r[q][h] + f2v[h];
                float e = fmaxf(s, 0.5f * s);            // LeakyReLU(0.5)
                float p = (m > 0) ? __expf(e) : 0.0f;    // no max-shift needed
                p_s[(h * TJ + lane) * PPAD + r] = p;
                dpart[q][h] += p;
            }
        }
        // prefetch Wh tile column (independent of smem)
        float whr[TJ];
#pragma unroll
        for (int jj = 0; jj < TJ; jj++)
            whr[jj] = Wh[(j0 + jj) * F_TOT + feat];
        __syncthreads();
        // ---- accumulate: LDS.128 of p pairs + packed fp32x2 FMA ----
#pragma unroll
        for (int jj = 0; jj < TJ; jj++) {
            u64 w2 = pack2(whr[jj], whr[jj]);
            const float* pb = &p_s[(hh * TJ + jj) * PPAD + r0t];
#pragma unroll
            for (int c = 0; c < RPT / 4; c++) {
                ulonglong2 pv = *(const ulonglong2*)(pb + 4 * c);
                acc[2 * c]     = fma2(pv.x, w2, acc[2 * c]);
                acc[2 * c + 1] = fma2(pv.y, w2, acc[2 * c + 1]);
            }
        }
        __syncthreads();
    }

    // ---- denominator: warp-reduce over jj (= lanes) ----
#pragma unroll
    for (int q = 0; q < 4; q++)
#pragma unroll
        for (int h = 0; h < NH; h++) {
            float v = dpart[q][h];
#pragma unroll
            for (int off = 16; off; off >>= 1)
                v += __shfl_down_sync(0xffffffffu, v, off);
            if (lane == 0) denom_s[(q * 8 + warp) * NH + h] = v;
        }
    __syncthreads();

    // ---- normalize + ELU + store ----
#pragma unroll
    for (int j = 0; j < RPT / 2; j++) {
        int ra = r0t + 2 * j;
        float va = lo2(acc[j]) / denom_s[ra * NH + hh];
        float vb = hi2(acc[j]) / denom_s[(ra + 1) * NH + hh];
        va = va > 0.0f ? va : expm1f(va);
        vb = vb > 0.0f ? vb : expm1f(vb);
        out[(row0 + ra) * F_TOT + feat]     = va;
        out[(row0 + ra + 1) * F_TOT + feat] = vb;
    }
}

__global__ void __launch_bounds__(256) attn1_k(const int* __restrict__ adj) {
    attn_body<F1T, NH1>(adj, g_Wh1, g_f1h, g_f2h, g_h1);
}
__global__ void __launch_bounds__(256) attn2_k(const int* __restrict__ adj,
                                               float* __restrict__ out) {
    attn_body<F2T, 1>(adj, g_Wh2, g_f1o, g_f2o, out);
}

// =======================================================================
extern "C" void kernel_launch(void* const* d_in, const int* in_sizes, int n_in,
                              void* d_out, int out_size) {
    const float* x       = (const float*)d_in[0];
    const int*   adj     = (const int*)  d_in[1];
    const float* W_heads = (const float*)d_in[2];
    const float* a_heads = (const float*)d_in[3];
    const float* W_out   = (const float*)d_in[4];
    const float* a_out   = (const float*)d_in[5];
    float* out = (float*)d_out;

    gemm1_k<<<NN / 64, 256>>>(x, W_heads);
    fvec1_k<<<NN, 64>>>(a_heads);
    attn1_k<<<NN / 32, 256>>>(adj);
    gemm2_k<<<NN / 64, 256>>>(W_out);
    fvec2_k<<<NN, 128>>>(a_out);
    attn2_k<<<NN / 32, 256>>>(adj, out);
}

// round 3
// speedup vs baseline: 1.1227x; 1.1227x over previous
#include <cuda_runtime.h>

#define NN   4096
#define IND  256
#define HID1 64
#define NH1  4
#define F1T  256
#define F2T  128

typedef unsigned long long u64;

// ---- scratch (device globals; no allocation allowed) ----
__device__ float g_Wh1[NN * F1T];   // layer-1 Wh, heads concatenated
__device__ float g_h1 [NN * F1T];   // layer-1 output (after ELU)
__device__ float g_Wh2[NN * F2T];
// factored-exp vectors: e1p=exp(f1), e1n=exp(f1/2), e2p=exp(f2), e2n=exp(f2/2)
__device__ float g_e1p_h[NH1 * NN], g_e1n_h[NH1 * NN];
__device__ float g_e2p_h[NH1 * NN], g_e2n_h[NH1 * NN];
__device__ float g_e1p_o[NN], g_e1n_o[NN], g_e2p_o[NN], g_e2n_o[NN];

// ---- packed fp32x2 helpers (sm_103a) ----
__device__ __forceinline__ u64 pack2(float lo, float hi) {
    return (u64)__float_as_uint(lo) | ((u64)__float_as_uint(hi) << 32);
}
__device__ __forceinline__ float lo2(u64 v) { return __uint_as_float((unsigned)v); }
__device__ __forceinline__ float hi2(u64 v) { return __uint_as_float((unsigned)(v >> 32)); }
__device__ __forceinline__ u64 fma2(u64 a, u64 b, u64 c) {
    u64 d;
    asm("fma.rn.f32x2 %0, %1, %2, %3;" : "=l"(d) : "l"(a), "l"(b), "l"(c));
    return d;
}

// =======================================================================
// GEMM: C[4096, FCOLS] = A[4096,256] @ B    (block = 64 rows, 256 threads)
// =======================================================================
template <int FCOLS, bool HEADS_B>
__device__ __forceinline__ void gemm_body(const float* __restrict__ A,
                                          const float* __restrict__ B,
                                          float* __restrict__ C) {
    constexpr int K = 256, XPAD = 68;
    constexpr int NRG = 256 / FCOLS;
    constexpr int RPT = 64 / NRG;            // rows per thread
    const int tid  = threadIdx.x;
    const int col  = tid % FCOLS;
    const int r0t  = (tid / FCOLS) * RPT;
    const int row0 = blockIdx.x * 64;

    __shared__ float x_s[32 * XPAD];         // [kk][r], padded

    u64 acc[RPT / 2];
#pragma unroll
    for (int j = 0; j < RPT / 2; j++) acc[j] = 0ull;

    for (int k0 = 0; k0 < K; k0 += 32) {
        __syncthreads();
#pragma unroll
        for (int i = 0; i < 8; i++) {
            int idx = i * 256 + tid;
            int r = idx >> 5, kk = idx & 31;
            x_s[kk * XPAD + r] = A[(row0 + r) * K + k0 + kk];
        }
        float bv[32];
#pragma unroll
        for (int kk = 0; kk < 32; kk++)
            bv[kk] = HEADS_B
                   ? B[(col >> 6) * (IND * HID1) + (k0 + kk) * HID1 + (col & 63)]
                   : B[(k0 + kk) * FCOLS + col];
        __syncthreads();
#pragma unroll
        for (int kk = 0; kk < 32; kk++) {
            u64 b2 = pack2(bv[kk], bv[kk]);
            const float* xb = &x_s[kk * XPAD + r0t];
#pragma unroll
            for (int c = 0; c < RPT / 4; c++) {
                ulonglong2 xv = *(const ulonglong2*)(xb + 4 * c);
                acc[2 * c]     = fma2(xv.x, b2, acc[2 * c]);
                acc[2 * c + 1] = fma2(xv.y, b2, acc[2 * c + 1]);
            }
        }
    }
#pragma unroll
    for (int j = 0; j < RPT / 2; j++) {
        C[(row0 + r0t + 2 * j)     * FCOLS + col] = lo2(acc[j]);
        C[(row0 + r0t + 2 * j + 1) * FCOLS + col] = hi2(acc[j]);
    }
}

__global__ void __launch_bounds__(256) gemm1_k(const float* __restrict__ x,
                                               const float* __restrict__ W_heads) {
    gemm_body<F1T, true>(x, W_heads, g_Wh1);
}
__global__ void __launch_bounds__(256) gemm2_k(const float* __restrict__ W_out) {
    gemm_body<F2T, false>(g_h1, W_out, g_Wh2);
}

// =======================================================================
// f-vector kernels: f1 = Wh . a[:F], f2 = Wh . a[F:], then store exp forms
// =======================================================================
__global__ void fvec1_k(const float* __restrict__ a_heads) {
    const int i = blockIdx.x;
    const int t = threadIdx.x;            // 0..63
    const int lane = t & 31, w = t >> 5;
    float p1[NH1], p2[NH1];
#pragma unroll
    for (int h = 0; h < NH1; h++) {
        float v = g_Wh1[i * F1T + h * HID1 + t];
        p1[h] = v * a_heads[h * (2 * HID1) + t];
        p2[h] = v * a_heads[h * (2 * HID1) + HID1 + t];
    }
#pragma unroll
    for (int off = 16; off; off >>= 1)
#pragma unroll
        for (int h = 0; h < NH1; h++) {
            p1[h] += __shfl_down_sync(0xffffffffu, p1[h], off);
            p2[h] += __shfl_down_sync(0xffffffffu, p2[h], off);
        }
    __shared__ float red[2][2 * NH1];
    if (lane == 0) {
#pragma unroll
        for (int h = 0; h < NH1; h++) { red[w][h] = p1[h]; red[w][NH1 + h] = p2[h]; }
    }
    __syncthreads();
    if (t == 0) {
#pragma unroll
        for (int h = 0; h < NH1; h++) {
            float f1 = red[0][h] + red[1][h];
            float f2 = red[0][NH1 + h] + red[1][NH1 + h];
            g_e1p_h[h * NN + i] = __expf(f1);
            g_e1n_h[h * NN + i] = __expf(0.5f * f1);
            g_e2p_h[h * NN + i] = __expf(f2);
            g_e2n_h[h * NN + i] = __expf(0.5f * f2);
        }
    }
}

__global__ void fvec2_k(const float* __restrict__ a_out) {
    const int i = blockIdx.x;
    const int t = threadIdx.x;            // 0..127
    const int lane = t & 31, w = t >> 5;
    float v  = g_Wh2[i * F2T + t];
    float p1 = v * a_out[t];
    float p2 = v * a_out[F2T + t];
#pragma unroll
    for (int off = 16; off; off >>= 1) {
        p1 += __shfl_down_sync(0xffffffffu, p1, off);
        p2 += __shfl_down_sync(0xffffffffu, p2, off);
    }
    __shared__ float red[4][2];
    if (lane == 0) { red[w][0] = p1; red[w][1] = p2; }
    __syncthreads();
    if (t == 0) {
        float f1 = red[0][0] + red[1][0] + red[2][0] + red[3][0];
        float f2 = red[0][1] + red[1][1] + red[2][1] + red[3][1];
        g_e1p_o[i] = __expf(f1);
        g_e1n_o[i] = __expf(0.5f * f1);
        g_e2p_o[i] = __expf(f2);
        g_e2n_o[i] = __expf(0.5f * f2);
    }
}

// =======================================================================
// Fused masked-softmax attention + aggregation + ELU (flash style)
// block = 32 rows x all F_TOT feats, 512 threads (16 warps), 32-wide j-tiles
// p = mask * max(e1p[i]*e2p[j], e1n[i]*e2n[j])   (== mask*exp(leakyrelu))
// =======================================================================
template <int F_TOT, int NH>
__device__ __forceinline__ void attn_body(const int* __restrict__ adj,
                                          const float* __restrict__ Wh,
                                          const float* __restrict__ e1p,
                                          const float* __restrict__ e1n,
                                          const float* __restrict__ e2p,
                                          const float* __restrict__ e2n,
                                          float* __restrict__ out) {
    constexpr int TI = 32, TJ = 32, PPAD = 36;
    constexpr int NT = 512, NW = 16;
    constexpr int HID = F_TOT / NH;
    constexpr int NRG = NT / F_TOT;              // 2 (L1), 4 (L2)
    constexpr int RPT = TI / NRG;                // 16, 8
    constexpr int NQ  = TI / NW;                 // 2
    const int tid  = threadIdx.x;
    const int lane = tid & 31, warp = tid >> 5;
    const int row0 = blockIdx.x * TI;
    const int feat = tid % F_TOT;
    const int r0t  = (tid / F_TOT) * RPT;
    const int hh   = feat / HID;

    __shared__ float p_s[NH * TJ * PPAD];        // [h][jj][r], padded 36
    __shared__ float denom_s[TI * NH];

    u64 acc[RPT / 2];
#pragma unroll
    for (int j = 0; j < RPT / 2; j++) acc[j] = 0ull;

    float dpart[NQ][NH];
#pragma unroll
    for (int q = 0; q < NQ; q++)
#pragma unroll
        for (int h = 0; h < NH; h++) dpart[q][h] = 0.0f;

    float E1p[NQ][NH], E1n[NQ][NH];              // row factors (registers)
#pragma unroll
    for (int q = 0; q < NQ; q++)
#pragma unroll
        for (int h = 0; h < NH; h++) {
            E1p[q][h] = e1p[h * NN + row0 + q * NW + warp];
            E1n[q][h] = e1n[h * NN + row0 + q * NW + warp];
        }

    for (int j0 = 0; j0 < NN; j0 += TJ) {
        // ---- p phase: thread handles (jj = lane, r = q*16 + warp) ----
        float E2pv[NH], E2nv[NH];
#pragma unroll
        for (int h = 0; h < NH; h++) {
            E2pv[h] = e2p[h * NN + j0 + lane];
            E2nv[h] = e2n[h * NN + j0 + lane];
        }
#pragma unroll
        for (int q = 0; q < NQ; q++) {
            const int r = q * NW + warp;
            const int m = adj[(row0 + r) * NN + j0 + lane];
#pragma unroll
            for (int h = 0; h < NH; h++) {
                float pa = E1p[q][h] * E2pv[h];
                float pb = E1n[q][h] * E2nv[h];
                float p  = (m > 0) ? fmaxf(pa, pb) : 0.0f;
                p_s[(h * TJ + lane) * PPAD + r] = p;
                dpart[q][h] += p;
            }
        }
        // prefetch Wh tile column (independent of smem)
        float whr[TJ];
#pragma unroll
        for (int jj = 0; jj < TJ; jj++)
            whr[jj] = Wh[(j0 + jj) * F_TOT + feat];
        __syncthreads();
        // ---- accumulate: LDS.128 of p pairs + packed fp32x2 FMA ----
#pragma unroll
        for (int jj = 0; jj < TJ; jj++) {
            u64 w2 = pack2(whr[jj], whr[jj]);
            const float* pb_ = &p_s[(hh * TJ + jj) * PPAD + r0t];
#pragma unroll
            for (int c = 0; c < RPT / 4; c++) {
                ulonglong2 pv = *(const ulonglong2*)(pb_ + 4 * c);
                acc[2 * c]     = fma2(pv.x, w2, acc[2 * c]);
                acc[2 * c + 1] = fma2(pv.y, w2, acc[2 * c + 1]);
            }
        }
        __syncthreads();
    }

    // ---- denominator: warp-reduce over jj (= lanes) ----
#pragma unroll
    for (int q = 0; q < NQ; q++)
#pragma unroll
        for (int h = 0; h < NH; h++) {
            float v = dpart[q][h];
#pragma unroll
            for (int off = 16; off; off >>= 1)
                v += __shfl_down_sync(0xffffffffu, v, off);
            if (lane == 0) denom_s[(q * NW + warp) * NH + h] = v;
        }
    __syncthreads();

    // ---- normalize + ELU + store ----
#pragma unroll
    for (int j = 0; j < RPT / 2; j++) {
        int ra = r0t + 2 * j;
        float va = lo2(acc[j]) / denom_s[ra * NH + hh];
        float vb = hi2(acc[j]) / denom_s[(ra + 1) * NH + hh];
        va = va > 0.0f ? va : expm1f(va);
        vb = vb > 0.0f ? vb : expm1f(vb);
        out[(row0 + ra) * F_TOT + feat]     = va;
        out[(row0 + ra + 1) * F_TOT + feat] = vb;
    }
}

__global__ void __launch_bounds__(512) attn1_k(const int* __restrict__ adj) {
    attn_body<F1T, NH1>(adj, g_Wh1, g_e1p_h, g_e1n_h, g_e2p_h, g_e2n_h, g_h1);
}
__global__ void __launch_bounds__(512) attn2_k(const int* __restrict__ adj,
                                               float* __restrict__ out) {
    attn_body<F2T, 1>(adj, g_Wh2, g_e1p_o, g_e1n_o, g_e2p_o, g_e2n_o, out);
}

// =======================================================================
extern "C" void kernel_launch(void* const* d_in, const int* in_sizes, int n_in,
                              void* d_out, int out_size) {
    const float* x       = (const float*)d_in[0];
    const int*   adj     = (const int*)  d_in[1];
    const float* W_heads = (const float*)d_in[2];
    const float* a_heads = (const float*)d_in[3];
    const float* W_out   = (const float*)d_in[4];
    const float* a_out   = (const float*)d_in[5];
    float* out = (float*)d_out;

    gemm1_k<<<NN / 64, 256>>>(x, W_heads);
    fvec1_k<<<NN, 64>>>(a_heads);
    attn1_k<<<NN / 32, 512>>>(adj);
    gemm2_k<<<NN / 64, 256>>>(W_out);
    fvec2_k<<<NN, 128>>>(a_out);
    attn2_k<<<NN / 32, 512>>>(adj, out);
}